// round 10
// baseline (speedup 1.0000x reference)
#include <cuda_runtime.h>
#include <cuda_fp16.h>
#include <cstdint>

// ---------------------------------------------------------------------------
// TargetTokenEncoder: hist/stats -> MLP(14->256, exact GELU) -> GEMM(256x256)
// Stage C via warp-level HMMA (mma.sync m16n8k16 f16, fp32 accum),
// fp16x2 split: A single fp16 plane, B split fp16 hi+lo (rel err ~2e-4).
// R10: __launch_bounds__(256,4) -> 4 CTAs/SM (32 warps). Register diet:
//      no explicit B prefetch (occupancy hides LDG), per-cgp frag loads,
//      incremental pointer addressing (alu diet). Barrier-free GEMM.
// ---------------------------------------------------------------------------

static constexpr int S      = 128;
static constexpr int TD     = 256;
static constexpr int TILE_M = 32;

static constexpr int A_STRIDE = 528;   // 256 fp16 + 8 pad (odd 16B multiple)
static constexpr int OFF_A     = 0;    // 32 x 528 = 16896
static constexpr int OFF_STATS = 16896;  // 32 x 16 f32 = 2048
static constexpr int SMEM_BYTES = 19456; // x4 CTAs = 77824 < 228KB

// B fragment scratch: [ks 0..15][cgpair 0..15][lane 0..31][8 fp16]
// Element (e): cg = 2*cgp + (e>>2), k = ks*16 + 2*(L%4) + ((e&2)?8:0) + (e&1),
//              n = cg*8 + L/4, value = w2[k][n]. (layout verified R7/R8/R9)
__device__ __align__(16) __half g_b_hi[16 * 16 * 32 * 8];   // 128KB
__device__ __align__(16) __half g_b_lo[16 * 16 * 32 * 8];   // 128KB

__device__ __forceinline__ uint32_t smem_u32(const void* p) {
    uint32_t a;
    asm("{ .reg .u64 t; cvta.to.shared.u64 t, %1; cvt.u32.u64 %0, t; }" : "=r"(a) : "l"(p));
    return a;
}

__device__ __forceinline__ void ldm4(uint32_t* r, uint32_t addr) {
    asm volatile("ldmatrix.sync.aligned.m8n8.x4.shared.b16 {%0,%1,%2,%3}, [%4];"
                 : "=r"(r[0]), "=r"(r[1]), "=r"(r[2]), "=r"(r[3]) : "r"(addr));
}

__device__ __forceinline__ void mma_f16(float* c, const uint32_t* a,
                                        uint32_t b0, uint32_t b1) {
    asm volatile("mma.sync.aligned.m16n8k16.row.col.f32.f16.f16.f32 "
                 "{%0,%1,%2,%3}, {%4,%5,%6,%7}, {%8,%9}, {%0,%1,%2,%3};"
                 : "+f"(c[0]), "+f"(c[1]), "+f"(c[2]), "+f"(c[3])
                 : "r"(a[0]), "r"(a[1]), "r"(a[2]), "r"(a[3]), "r"(b0), "r"(b1));
}

// ---------------- prep kernel: w2 -> split fp16 fragment-order scratch
__global__ __launch_bounds__(256)
void prep_kernel(const float* __restrict__ w2) {
    int idx = blockIdx.x * 256 + threadIdx.x;          // (ks<<9)|(cgp<<5)|L
    if (idx >= 8192) return;
    const int L   = idx & 31;
    const int cgp = (idx >> 5) & 15;
    const int ks  = idx >> 9;
    const int k0  = ks * 16 + 2 * (L & 3);
    const int nb  = L >> 2;
    __half* oh = g_b_hi + (size_t)idx * 8;
    __half* ol = g_b_lo + (size_t)idx * 8;
    #pragma unroll
    for (int e = 0; e < 8; e++) {
        const int cg = cgp * 2 + (e >> 2);
        const int kk = k0 + ((e & 2) ? 8 : 0) + (e & 1);
        const int n  = cg * 8 + nb;
        float v = __ldg(w2 + (size_t)kk * TD + n);
        __half hi = __float2half_rn(v);
        float lo = v - __half2float(hi);
        oh[e] = hi;
        ol[e] = __float2half_rn(lo);
    }
}

__global__ __launch_bounds__(256, 4)
void tte_kernel(const int* __restrict__ y, const float* __restrict__ w1,
                const float* __restrict__ b1,
                const float* __restrict__ b2, float* __restrict__ out)
{
    extern __shared__ char smem[];
    const uint32_t sb = smem_u32(smem);
    const int tid = threadIdx.x;
    const int wid = tid >> 5;
    const int lid = tid & 31;

    float* stats = reinterpret_cast<float*>(smem + OFF_STATS);

    // ---------------- Phase 1: cooperative histogram, 8 threads per row
    {
        const int row = tid >> 3;             // 0..31
        const int sub = tid & 7;
        const int4* p = reinterpret_cast<const int4*>(
            y + ((size_t)blockIdx.x * TILE_M + row) * S) + sub * 4;
        uint32_t a0 = 0, a1 = 0, a2 = 0;      // 4x8-bit packed counters
        #pragma unroll
        for (int i = 0; i < 4; i++) {
            int4 v = __ldg(p + i);
            { int x = v.x; uint32_t b = 1u << ((x & 3) << 3);
              if (x < 4) a0 += b; else if (x < 8) a1 += b; else a2 += b; }
            { int x = v.y; uint32_t b = 1u << ((x & 3) << 3);
              if (x < 4) a0 += b; else if (x < 8) a1 += b; else a2 += b; }
            { int x = v.z; uint32_t b = 1u << ((x & 3) << 3);
              if (x < 4) a0 += b; else if (x < 8) a1 += b; else a2 += b; }
            { int x = v.w; uint32_t b = 1u << ((x & 3) << 3);
              if (x < 4) a0 += b; else if (x < 8) a1 += b; else a2 += b; }
        }
        #pragma unroll
        for (int d = 1; d < 8; d <<= 1) {
            a0 += __shfl_xor_sync(0xFFFFFFFFu, a0, d);
            a1 += __shfl_xor_sync(0xFFFFFFFFu, a1, d);
            a2 += __shfl_xor_sync(0xFFFFFFFFu, a2, d);
        }
        if (sub == 0) {
            int cnt[10];
            float pr[10];
            #pragma unroll
            for (int c = 0; c < 10; c++) {
                uint32_t a = (c < 4) ? a0 : ((c < 8) ? a1 : a2);
                cnt[c] = (int)((a >> ((c & 3) * 8)) & 0xFF);
                pr[c]  = (float)cnt[c] * (1.0f / 128.0f);   // exact in fp32
            }
            float ent = 0.0f, pm = 0.0f, nnz = 0.0f;
            #pragma unroll
            for (int c = 0; c < 10; c++) {
                ent -= pr[c] * logf(pr[c] + 1e-6f);         // p==0 -> exactly 0
                pm   = fmaxf(pm, pr[c]);
                nnz += (cnt[c] > 0) ? 1.0f : 0.0f;
            }
            float* sr = stats + row * 16;
            #pragma unroll
            for (int c = 0; c < 10; c++) sr[c] = pr[c];
            sr[10] = nnz; sr[11] = ent; sr[12] = 128.0f; sr[13] = pm;
            sr[14] = 0.0f; sr[15] = 0.0f;
        }
    }
    __syncthreads();

    // ---------------- Phase 2: stage-B MLP. thread t owns h column n=t.
    {
        float wv[14];
        #pragma unroll
        for (int k = 0; k < 14; k++) wv[k] = __ldg(w1 + k * TD + tid);
        const float bb = __ldg(b1 + tid);
        #pragma unroll 2
        for (int r = 0; r < TILE_M; r++) {
            const float4* sp = reinterpret_cast<const float4*>(stats + r * 16);
            float4 s0 = sp[0], s1 = sp[1], s2 = sp[2], s3 = sp[3];
            float x = bb;
            x = fmaf(s0.x, wv[0], x);  x = fmaf(s0.y, wv[1], x);
            x = fmaf(s0.z, wv[2], x);  x = fmaf(s0.w, wv[3], x);
            x = fmaf(s1.x, wv[4], x);  x = fmaf(s1.y, wv[5], x);
            x = fmaf(s1.z, wv[6], x);  x = fmaf(s1.w, wv[7], x);
            x = fmaf(s2.x, wv[8], x);  x = fmaf(s2.y, wv[9], x);
            x = fmaf(s2.z, wv[10], x); x = fmaf(s2.w, wv[11], x);
            x = fmaf(s3.x, wv[12], x); x = fmaf(s3.y, wv[13], x);
            float g = 0.5f * x * (1.0f + erff(x * 0.707106781186547524f));
            *reinterpret_cast<__half*>(smem + OFF_A
                + (uint32_t)(r * A_STRIDE + tid * 2)) = __float2half_rn(g);
        }
    }
    __syncthreads();   // last barrier — GEMM runs barrier-free

    // ---------------- Phase 3: GEMM h[32,256] @ w2 slice, fp16x2 HMMA.
    // Warp tile 32M x 32N: warp wid owns cols [wid*32, wid*32+32).
    const int j8 = lid >> 3;
    const int lr = lid & 7;

    uint32_t aoff0 = sb + OFF_A
        + (uint32_t)((((j8 & 1) << 3) + lr) * A_STRIDE) + (uint32_t)((j8 >> 1) << 4);
    uint32_t aoff1 = aoff0 + (uint32_t)(16 * A_STRIDE);

    // incremental fragment pointers (stride per ks = 16 cgp groups = 512 uint4)
    const uint4* ph = reinterpret_cast<const uint4*>(g_b_hi) + ((wid * 2) << 5) + lid;
    const uint4* pl = reinterpret_cast<const uint4*>(g_b_lo) + ((wid * 2) << 5) + lid;

    float acc[2][4][4];                // [mtile][cg][frag] = 32 regs
    #pragma unroll
    for (int i = 0; i < 2; i++)
        #pragma unroll
        for (int j = 0; j < 4; j++)
            #pragma unroll
            for (int q = 0; q < 4; q++) acc[i][j][q] = 0.0f;

    #pragma unroll
    for (int ks = 0; ks < 16; ks++) {
        uint32_t af[2][4];
        ldm4(af[0], aoff0);
        ldm4(af[1], aoff1);
        aoff0 += 32;
        aoff1 += 32;
        #pragma unroll
        for (int cgp = 0; cgp < 2; cgp++) {
            const uint4 bh = __ldg(ph + (cgp << 5));
            const uint4 bl = __ldg(pl + (cgp << 5));
            #pragma unroll
            for (int i = 0; i < 2; i++) {
                mma_f16(acc[i][cgp * 2],     af[i], bh.x, bh.y);   // A*Bh
                mma_f16(acc[i][cgp * 2],     af[i], bl.x, bl.y);   // A*Bl
                mma_f16(acc[i][cgp * 2 + 1], af[i], bh.z, bh.w);
                mma_f16(acc[i][cgp * 2 + 1], af[i], bl.z, bl.w);
            }
        }
        ph += 512;
        pl += 512;
    }

    // ---------------- Epilogue (b2 from gmem; L1/L2 resident)
    {
        const int g  = lid >> 2;
        const int tg = lid & 3;
        const size_t rbase = (size_t)blockIdx.x * TILE_M;
        #pragma unroll
        for (int i = 0; i < 2; i++) {
            #pragma unroll
            for (int cg = 0; cg < 4; cg++) {
                const int col = wid * 32 + cg * 8 + tg * 2;
                const float2 bbv = __ldg(reinterpret_cast<const float2*>(b2 + col));
                const size_t r0 = rbase + i * 16 + g;
                *reinterpret_cast<float2*>(out + r0 * TD + col) =
                    make_float2(acc[i][cg][0] + bbv.x, acc[i][cg][1] + bbv.y);
                *reinterpret_cast<float2*>(out + (r0 + 8) * TD + col) =
                    make_float2(acc[i][cg][2] + bbv.x, acc[i][cg][3] + bbv.y);
            }
        }
    }
}

extern "C" void kernel_launch(void* const* d_in, const int* in_sizes, int n_in,
                              void* d_out, int out_size) {
    const int*   y  = (const int*)d_in[0];
    const float* w1 = (const float*)d_in[1];
    const float* b1 = (const float*)d_in[2];
    const float* w2 = (const float*)d_in[3];
    const float* b2 = (const float*)d_in[4];
    float* out = (float*)d_out;
    const int Btot = in_sizes[0] / S;          // 65536 rows
    const int grid = Btot / TILE_M;            // 2048 CTAs

    prep_kernel<<<32, 256>>>(w2);              // 8192 fragment groups

    cudaFuncSetAttribute(tte_kernel, cudaFuncAttributeMaxDynamicSharedMemorySize,
                         SMEM_BYTES);
    tte_kernel<<<grid, 256, SMEM_BYTES>>>(y, w1, b1, b2, out);
}

// round 11
// speedup vs baseline: 1.2521x; 1.2521x over previous
#include <cuda_runtime.h>
#include <cuda_fp16.h>
#include <cstdint>

// ---------------------------------------------------------------------------
// TargetTokenEncoder: hist/stats -> MLP(14->256, exact GELU) -> GEMM(256x256)
// Stage C via warp-level HMMA (mma.sync m16n8k16 f16, fp32 accum),
// SINGLE-PASS fp16: A fp16, B fp16 (one plane).
//   err = deltaA*B (+) A*deltaB ~ sqrt(2)*1.46e-4 -> ~2.9e-4 rel (< 1e-3).
// R11: R9 structure (TILE_M=32, occ 3, prefetch pipeline, barrier-free GEMM)
//      minus the B-lo plane and second MMA pass.
// ---------------------------------------------------------------------------

static constexpr int S      = 128;
static constexpr int TD     = 256;
static constexpr int TILE_M = 32;

static constexpr int A_STRIDE = 528;   // 256 fp16 + 8 pad (odd 16B multiple)
static constexpr int OFF_A     = 0;    // 32 x 528 = 16896
static constexpr int OFF_STATS = 16896;  // 32 x 16 f32 = 2048
static constexpr int SMEM_BYTES = 19456;

// B fragment scratch: [ks 0..15][cgpair 0..15][lane 0..31][8 fp16]
// Element (e): cg = 2*cgp + (e>>2), k = ks*16 + 2*(L%4) + ((e&2)?8:0) + (e&1),
//              n = cg*8 + L/4, value = w2[k][n]. (layout verified R7..R10)
__device__ __align__(16) __half g_b[16 * 16 * 32 * 8];   // 128KB

__device__ __forceinline__ uint32_t smem_u32(const void* p) {
    uint32_t a;
    asm("{ .reg .u64 t; cvta.to.shared.u64 t, %1; cvt.u32.u64 %0, t; }" : "=r"(a) : "l"(p));
    return a;
}

__device__ __forceinline__ void ldm4(uint32_t* r, uint32_t addr) {
    asm volatile("ldmatrix.sync.aligned.m8n8.x4.shared.b16 {%0,%1,%2,%3}, [%4];"
                 : "=r"(r[0]), "=r"(r[1]), "=r"(r[2]), "=r"(r[3]) : "r"(addr));
}

__device__ __forceinline__ void mma_f16(float* c, const uint32_t* a,
                                        uint32_t b0, uint32_t b1) {
    asm volatile("mma.sync.aligned.m16n8k16.row.col.f32.f16.f16.f32 "
                 "{%0,%1,%2,%3}, {%4,%5,%6,%7}, {%8,%9}, {%0,%1,%2,%3};"
                 : "+f"(c[0]), "+f"(c[1]), "+f"(c[2]), "+f"(c[3])
                 : "r"(a[0]), "r"(a[1]), "r"(a[2]), "r"(a[3]), "r"(b0), "r"(b1));
}

// ---------------- prep kernel: w2 -> fp16 fragment-order scratch
__global__ __launch_bounds__(256)
void prep_kernel(const float* __restrict__ w2) {
    int idx = blockIdx.x * 256 + threadIdx.x;          // (ks<<9)|(cgp<<5)|L
    if (idx >= 8192) return;
    const int L   = idx & 31;
    const int cgp = (idx >> 5) & 15;
    const int ks  = idx >> 9;
    const int k0  = ks * 16 + 2 * (L & 3);
    const int nb  = L >> 2;
    __half* oh = g_b + (size_t)idx * 8;
    #pragma unroll
    for (int e = 0; e < 8; e++) {
        const int cg = cgp * 2 + (e >> 2);
        const int kk = k0 + ((e & 2) ? 8 : 0) + (e & 1);
        const int n  = cg * 8 + nb;
        oh[e] = __float2half_rn(__ldg(w2 + (size_t)kk * TD + n));
    }
}

__global__ __launch_bounds__(256, 3)
void tte_kernel(const int* __restrict__ y, const float* __restrict__ w1,
                const float* __restrict__ b1,
                const float* __restrict__ b2, float* __restrict__ out)
{
    extern __shared__ char smem[];
    const uint32_t sb = smem_u32(smem);
    const int tid = threadIdx.x;
    const int wid = tid >> 5;
    const int lid = tid & 31;

    float* stats = reinterpret_cast<float*>(smem + OFF_STATS);

    // ---------------- Phase 1: cooperative histogram, 8 threads per row
    {
        const int row = tid >> 3;             // 0..31
        const int sub = tid & 7;
        const int4* p = reinterpret_cast<const int4*>(
            y + ((size_t)blockIdx.x * TILE_M + row) * S) + sub * 4;
        uint32_t a0 = 0, a1 = 0, a2 = 0;      // 4x8-bit packed counters
        #pragma unroll
        for (int i = 0; i < 4; i++) {
            int4 v = __ldg(p + i);
            { int x = v.x; uint32_t b = 1u << ((x & 3) << 3);
              if (x < 4) a0 += b; else if (x < 8) a1 += b; else a2 += b; }
            { int x = v.y; uint32_t b = 1u << ((x & 3) << 3);
              if (x < 4) a0 += b; else if (x < 8) a1 += b; else a2 += b; }
            { int x = v.z; uint32_t b = 1u << ((x & 3) << 3);
              if (x < 4) a0 += b; else if (x < 8) a1 += b; else a2 += b; }
            { int x = v.w; uint32_t b = 1u << ((x & 3) << 3);
              if (x < 4) a0 += b; else if (x < 8) a1 += b; else a2 += b; }
        }
        #pragma unroll
        for (int d = 1; d < 8; d <<= 1) {
            a0 += __shfl_xor_sync(0xFFFFFFFFu, a0, d);
            a1 += __shfl_xor_sync(0xFFFFFFFFu, a1, d);
            a2 += __shfl_xor_sync(0xFFFFFFFFu, a2, d);
        }
        if (sub == 0) {
            int cnt[10];
            float pr[10];
            #pragma unroll
            for (int c = 0; c < 10; c++) {
                uint32_t a = (c < 4) ? a0 : ((c < 8) ? a1 : a2);
                cnt[c] = (int)((a >> ((c & 3) * 8)) & 0xFF);
                pr[c]  = (float)cnt[c] * (1.0f / 128.0f);   // exact in fp32
            }
            float ent = 0.0f, pm = 0.0f, nnz = 0.0f;
            #pragma unroll
            for (int c = 0; c < 10; c++) {
                ent -= pr[c] * logf(pr[c] + 1e-6f);         // p==0 -> exactly 0
                pm   = fmaxf(pm, pr[c]);
                nnz += (cnt[c] > 0) ? 1.0f : 0.0f;
            }
            float* sr = stats + row * 16;
            #pragma unroll
            for (int c = 0; c < 10; c++) sr[c] = pr[c];
            sr[10] = nnz; sr[11] = ent; sr[12] = 128.0f; sr[13] = pm;
            sr[14] = 0.0f; sr[15] = 0.0f;
        }
    }
    __syncthreads();

    // ---------------- Phase 2: stage-B MLP. thread t owns h column n=t.
    {
        float wv[14];
        #pragma unroll
        for (int k = 0; k < 14; k++) wv[k] = __ldg(w1 + k * TD + tid);
        const float bb = __ldg(b1 + tid);
        #pragma unroll 4
        for (int r = 0; r < TILE_M; r++) {
            const float4* sp = reinterpret_cast<const float4*>(stats + r * 16);
            float4 s0 = sp[0], s1 = sp[1], s2 = sp[2], s3 = sp[3];
            float x = bb;
            x = fmaf(s0.x, wv[0], x);  x = fmaf(s0.y, wv[1], x);
            x = fmaf(s0.z, wv[2], x);  x = fmaf(s0.w, wv[3], x);
            x = fmaf(s1.x, wv[4], x);  x = fmaf(s1.y, wv[5], x);
            x = fmaf(s1.z, wv[6], x);  x = fmaf(s1.w, wv[7], x);
            x = fmaf(s2.x, wv[8], x);  x = fmaf(s2.y, wv[9], x);
            x = fmaf(s2.z, wv[10], x); x = fmaf(s2.w, wv[11], x);
            x = fmaf(s3.x, wv[12], x); x = fmaf(s3.y, wv[13], x);
            float g = 0.5f * x * (1.0f + erff(x * 0.707106781186547524f));
            *reinterpret_cast<__half*>(smem + OFF_A
                + (uint32_t)(r * A_STRIDE + tid * 2)) = __float2half_rn(g);
        }
    }
    __syncthreads();   // last barrier — GEMM runs barrier-free

    // ---------------- Phase 3: GEMM h[32,256] @ w2 slice, fp16 HMMA (1 pass)
    // Warp tile 32M x 32N: warp wid owns cols [wid*32, wid*32+32).
    const int wn = wid;                // 0..7
    const int j8 = lid >> 3;
    const int lr = lid & 7;

    uint32_t aoff[2];                  // 2 m-tiles of 16 rows
    #pragma unroll
    for (int i = 0; i < 2; i++)
        aoff[i] = sb + OFF_A
                + (uint32_t)((i * 16 + ((j8 & 1) << 3) + lr) * A_STRIDE)
                + (uint32_t)((j8 >> 1) << 4);

    const uint4* gb = reinterpret_cast<const uint4*>(g_b);

    float acc[2][4][4];                // [mtile][cg][frag] = 32 regs
    #pragma unroll
    for (int i = 0; i < 2; i++)
        #pragma unroll
        for (int j = 0; j < 4; j++)
            #pragma unroll
            for (int q = 0; q < 4; q++) acc[i][j][q] = 0.0f;

    // prefetch pipeline: B fragments for ks=0
    uint4 fB[2];
    #pragma unroll
    for (int c = 0; c < 2; c++)
        fB[c] = __ldg(gb + (((wn * 2 + c) << 5) + lid));

    #pragma unroll
    for (int ks = 0; ks < 16; ks++) {
        uint4 nB[2];
        if (ks < 15) {
            #pragma unroll
            for (int c = 0; c < 2; c++)
                nB[c] = __ldg(gb + ((((ks + 1) * 16 + wn * 2 + c) << 5) + lid));
        }
        const uint32_t ka = (uint32_t)(ks * 32);
        uint32_t af[2][4];
        #pragma unroll
        for (int i = 0; i < 2; i++) ldm4(af[i], aoff[i] + ka);
        #pragma unroll
        for (int i = 0; i < 2; i++) {
            #pragma unroll
            for (int cg = 0; cg < 4; cg++) {
                const uint4& bh = fB[cg >> 1];
                const uint32_t b0 = (cg & 1) ? bh.z : bh.x;
                const uint32_t b1 = (cg & 1) ? bh.w : bh.y;
                mma_f16(acc[i][cg], af[i], b0, b1);
            }
        }
        #pragma unroll
        for (int c = 0; c < 2; c++) fB[c] = nB[c];
    }

    // ---------------- Epilogue (b2 from gmem; L1/L2 resident)
    {
        const int g  = lid >> 2;
        const int tg = lid & 3;
        const size_t rbase = (size_t)blockIdx.x * TILE_M;
        #pragma unroll
        for (int i = 0; i < 2; i++) {
            #pragma unroll
            for (int cg = 0; cg < 4; cg++) {
                const int col = wn * 32 + cg * 8 + tg * 2;
                const float2 bbv = __ldg(reinterpret_cast<const float2*>(b2 + col));
                const size_t r0 = rbase + i * 16 + g;
                *reinterpret_cast<float2*>(out + r0 * TD + col) =
                    make_float2(acc[i][cg][0] + bbv.x, acc[i][cg][1] + bbv.y);
                *reinterpret_cast<float2*>(out + (r0 + 8) * TD + col) =
                    make_float2(acc[i][cg][2] + bbv.x, acc[i][cg][3] + bbv.y);
            }
        }
    }
}

extern "C" void kernel_launch(void* const* d_in, const int* in_sizes, int n_in,
                              void* d_out, int out_size) {
    const int*   y  = (const int*)d_in[0];
    const float* w1 = (const float*)d_in[1];
    const float* b1 = (const float*)d_in[2];
    const float* w2 = (const float*)d_in[3];
    const float* b2 = (const float*)d_in[4];
    float* out = (float*)d_out;
    const int Btot = in_sizes[0] / S;          // 65536 rows
    const int grid = Btot / TILE_M;            // 2048 CTAs

    prep_kernel<<<32, 256>>>(w2);              // 8192 fragment groups

    cudaFuncSetAttribute(tte_kernel, cudaFuncAttributeMaxDynamicSharedMemorySize,
                         SMEM_BYTES);
    tte_kernel<<<grid, 256, SMEM_BYTES>>>(y, w1, b1, b2, out);
}

// round 13
// speedup vs baseline: 1.4358x; 1.1467x over previous
#include <cuda_runtime.h>
#include <cuda_fp16.h>
#include <cstdint>

// ---------------------------------------------------------------------------
// TargetTokenEncoder: hist/stats -> MLP(14->256, exact GELU) -> GEMM(256x256)
// Both GEMMs on tensor cores (mma.sync m16n8k16 f16, fp32 accum):
//   stage B: stats(fp16, exact except entropy) @ w1(fp16 hi+lo, 2 passes)
//   stage C: h(fp16) @ w2(fp16, 1 pass)           rel err ~3e-4 total
// R13: R12 with STATS_STRIDE fixed 40 -> 48 (ldmatrix needs 16B-aligned rows).
// ---------------------------------------------------------------------------

static constexpr int S      = 128;
static constexpr int TD     = 256;
static constexpr int TILE_M = 32;

static constexpr int A_STRIDE = 528;     // 256 fp16 + 8 pad
static constexpr int OFF_A     = 0;      // 32 x 528 = 16896
static constexpr int OFF_STATS = 16896;  // 32 rows x 48B (16 fp16 + 16 pad)
static constexpr int STATS_STRIDE = 48;  // 16B multiple (ldmatrix), odd granule
static constexpr int SMEM_BYTES = 18432;

// w2 fragment scratch: [ks 0..15][cgpair 0..15][lane 0..31][8 fp16]
// Element (e): cg = 2*cgp + (e>>2), k = ks*16 + 2*(L%4) + ((e&2)?8:0) + (e&1),
//              n = cg*8 + L/4, value = w2[k][n]. (layout verified R7..R11)
__device__ __align__(16) __half g_b[16 * 16 * 32 * 8];     // 128KB
// w1 fragment scratch (single ks, K=16 with rows 14,15 zero): hi + lo planes
__device__ __align__(16) __half g_w1h[16 * 32 * 8];        // 8KB
__device__ __align__(16) __half g_w1l[16 * 32 * 8];        // 8KB

__device__ __forceinline__ uint32_t smem_u32(const void* p) {
    uint32_t a;
    asm("{ .reg .u64 t; cvta.to.shared.u64 t, %1; cvt.u32.u64 %0, t; }" : "=r"(a) : "l"(p));
    return a;
}

__device__ __forceinline__ void ldm4(uint32_t* r, uint32_t addr) {
    asm volatile("ldmatrix.sync.aligned.m8n8.x4.shared.b16 {%0,%1,%2,%3}, [%4];"
                 : "=r"(r[0]), "=r"(r[1]), "=r"(r[2]), "=r"(r[3]) : "r"(addr));
}

__device__ __forceinline__ void mma_f16(float* c, const uint32_t* a,
                                        uint32_t b0, uint32_t b1) {
    asm volatile("mma.sync.aligned.m16n8k16.row.col.f32.f16.f16.f32 "
                 "{%0,%1,%2,%3}, {%4,%5,%6,%7}, {%8,%9}, {%0,%1,%2,%3};"
                 : "+f"(c[0]), "+f"(c[1]), "+f"(c[2]), "+f"(c[3])
                 : "r"(a[0]), "r"(a[1]), "r"(a[2]), "r"(a[3]), "r"(b0), "r"(b1));
}

__device__ __forceinline__ float gelu_exact(float x) {
    return 0.5f * x * (1.0f + erff(x * 0.707106781186547524f));
}

// ---------------- prep: w2 -> fp16 fragment scratch
__global__ __launch_bounds__(256)
void prep_kernel(const float* __restrict__ w2) {
    int idx = blockIdx.x * 256 + threadIdx.x;          // (ks<<9)|(cgp<<5)|L
    if (idx >= 8192) return;
    const int L   = idx & 31;
    const int cgp = (idx >> 5) & 15;
    const int ks  = idx >> 9;
    const int k0  = ks * 16 + 2 * (L & 3);
    const int nb  = L >> 2;
    __half* oh = g_b + (size_t)idx * 8;
    #pragma unroll
    for (int e = 0; e < 8; e++) {
        const int cg = cgp * 2 + (e >> 2);
        const int kk = k0 + ((e & 2) ? 8 : 0) + (e & 1);
        const int n  = cg * 8 + nb;
        oh[e] = __float2half_rn(__ldg(w2 + (size_t)kk * TD + n));
    }
}

// ---------------- prep2: w1 -> split fp16 fragment scratch (K=16, rows>=14 = 0)
__global__ __launch_bounds__(512)
void prep2_kernel(const float* __restrict__ w1) {
    int idx = threadIdx.x;                             // (cgp<<5)|L , 512 total
    const int L   = idx & 31;
    const int cgp = idx >> 5;
    const int k0  = 2 * (L & 3);
    const int nb  = L >> 2;
    __half* oh = g_w1h + (size_t)idx * 8;
    __half* ol = g_w1l + (size_t)idx * 8;
    #pragma unroll
    for (int e = 0; e < 8; e++) {
        const int cg = cgp * 2 + (e >> 2);
        const int kk = k0 + ((e & 2) ? 8 : 0) + (e & 1);
        const int n  = cg * 8 + nb;
        float v = (kk < 14) ? __ldg(w1 + (size_t)kk * TD + n) : 0.0f;
        __half hi = __float2half_rn(v);
        float lo = v - __half2float(hi);
        oh[e] = hi;
        ol[e] = __float2half_rn(lo);
    }
}

__global__ __launch_bounds__(256, 3)
void tte_kernel(const int* __restrict__ y, const float* __restrict__ w1,
                const float* __restrict__ b1,
                const float* __restrict__ b2, float* __restrict__ out)
{
    extern __shared__ char smem[];
    const uint32_t sb = smem_u32(smem);
    const int tid = threadIdx.x;
    const int wid = tid >> 5;
    const int lid = tid & 31;

    // ---------------- Phase 1: cooperative histogram, 8 threads per row
    {
        const int row = tid >> 3;             // 0..31
        const int sub = tid & 7;
        const int4* p = reinterpret_cast<const int4*>(
            y + ((size_t)blockIdx.x * TILE_M + row) * S) + sub * 4;
        uint32_t a0 = 0, a1 = 0, a2 = 0;      // 4x8-bit packed counters
        #pragma unroll
        for (int i = 0; i < 4; i++) {
            int4 v = __ldg(p + i);
            { int x = v.x; uint32_t b = 1u << ((x & 3) << 3);
              if (x < 4) a0 += b; else if (x < 8) a1 += b; else a2 += b; }
            { int x = v.y; uint32_t b = 1u << ((x & 3) << 3);
              if (x < 4) a0 += b; else if (x < 8) a1 += b; else a2 += b; }
            { int x = v.z; uint32_t b = 1u << ((x & 3) << 3);
              if (x < 4) a0 += b; else if (x < 8) a1 += b; else a2 += b; }
            { int x = v.w; uint32_t b = 1u << ((x & 3) << 3);
              if (x < 4) a0 += b; else if (x < 8) a1 += b; else a2 += b; }
        }
        #pragma unroll
        for (int d = 1; d < 8; d <<= 1) {
            a0 += __shfl_xor_sync(0xFFFFFFFFu, a0, d);
            a1 += __shfl_xor_sync(0xFFFFFFFFu, a1, d);
            a2 += __shfl_xor_sync(0xFFFFFFFFu, a2, d);
        }
        if (sub == 0) {
            int cnt[10];
            float pr[10];
            #pragma unroll
            for (int c = 0; c < 10; c++) {
                uint32_t a = (c < 4) ? a0 : ((c < 8) ? a1 : a2);
                cnt[c] = (int)((a >> ((c & 3) * 8)) & 0xFF);
                pr[c]  = (float)cnt[c] * (1.0f / 128.0f);   // exact in fp32/fp16
            }
            float ent = 0.0f, pm = 0.0f, nnz = 0.0f;
            #pragma unroll
            for (int c = 0; c < 10; c++) {
                ent -= pr[c] * logf(pr[c] + 1e-6f);         // p==0 -> exactly 0
                pm   = fmaxf(pm, pr[c]);
                nnz += (cnt[c] > 0) ? 1.0f : 0.0f;
            }
            // stats row as fp16 [16] (cols 14,15 zero)
            __half2* sr = reinterpret_cast<__half2*>(smem + OFF_STATS
                                                     + row * STATS_STRIDE);
            sr[0] = __floats2half2_rn(pr[0], pr[1]);
            sr[1] = __floats2half2_rn(pr[2], pr[3]);
            sr[2] = __floats2half2_rn(pr[4], pr[5]);
            sr[3] = __floats2half2_rn(pr[6], pr[7]);
            sr[4] = __floats2half2_rn(pr[8], pr[9]);
            sr[5] = __floats2half2_rn(nnz, ent);
            sr[6] = __floats2half2_rn(128.0f, pm);
            sr[7] = __floats2half2_rn(0.0f, 0.0f);
        }
    }
    __syncthreads();

    // warp/lane geometry shared by both GEMMs
    const int wn = wid;                // warp owns cols [wn*32, wn*32+32)
    const int j8 = lid >> 3;
    const int lr = lid & 7;
    const int g  = lid >> 2;
    const int tg = lid & 3;

    // ---------------- Phase 2: stage B = stats[32,16] @ w1[16,256] via HMMA,
    //                  + b1, exact GELU, h -> A smem (fp16)
    {
        uint32_t afS[2][4];
        #pragma unroll
        for (int i = 0; i < 2; i++) {
            const uint32_t ad = sb + OFF_STATS
                + (uint32_t)((i * 16 + ((j8 & 1) << 3) + lr) * STATS_STRIDE)
                + (uint32_t)((j8 >> 1) << 4);
            ldm4(afS[i], ad);
        }
        const uint4* gwh = reinterpret_cast<const uint4*>(g_w1h);
        const uint4* gwl = reinterpret_cast<const uint4*>(g_w1l);
        uint4 fh[2], fl[2];
        #pragma unroll
        for (int c = 0; c < 2; c++) {
            fh[c] = __ldg(gwh + (((wn * 2 + c) << 5) + lid));
            fl[c] = __ldg(gwl + (((wn * 2 + c) << 5) + lid));
        }
        float accS[2][4][4];
        #pragma unroll
        for (int i = 0; i < 2; i++)
            #pragma unroll
            for (int j = 0; j < 4; j++)
                #pragma unroll
                for (int q = 0; q < 4; q++) accS[i][j][q] = 0.0f;
        #pragma unroll
        for (int i = 0; i < 2; i++) {
            #pragma unroll
            for (int cg = 0; cg < 4; cg++) {
                const uint4& bh = fh[cg >> 1];
                const uint4& bl = fl[cg >> 1];
                const uint32_t h0 = (cg & 1) ? bh.z : bh.x;
                const uint32_t h1 = (cg & 1) ? bh.w : bh.y;
                const uint32_t l0 = (cg & 1) ? bl.z : bl.x;
                const uint32_t l1 = (cg & 1) ? bl.w : bl.y;
                mma_f16(accS[i][cg], afS[i], h0, h1);   // S*W1h
                mma_f16(accS[i][cg], afS[i], l0, l1);   // S*W1l
            }
        }
        // + b1, GELU, store h (half2) into A layout
        #pragma unroll
        for (int i = 0; i < 2; i++) {
            #pragma unroll
            for (int cg = 0; cg < 4; cg++) {
                const int col = wn * 32 + cg * 8 + tg * 2;
                const float2 bv = __ldg(reinterpret_cast<const float2*>(b1 + col));
                const float g0 = gelu_exact(accS[i][cg][0] + bv.x);
                const float g1 = gelu_exact(accS[i][cg][1] + bv.y);
                const float g2 = gelu_exact(accS[i][cg][2] + bv.x);
                const float g3 = gelu_exact(accS[i][cg][3] + bv.y);
                const int r0 = i * 16 + g;
                *reinterpret_cast<__half2*>(smem + OFF_A
                    + (uint32_t)(r0 * A_STRIDE + col * 2)) = __floats2half2_rn(g0, g1);
                *reinterpret_cast<__half2*>(smem + OFF_A
                    + (uint32_t)((r0 + 8) * A_STRIDE + col * 2)) = __floats2half2_rn(g2, g3);
            }
        }
    }
    __syncthreads();   // last barrier — stage C runs barrier-free

    // ---------------- Phase 3: GEMM h[32,256] @ w2 slice, fp16 HMMA (1 pass)
    uint32_t aoff[2];
    #pragma unroll
    for (int i = 0; i < 2; i++)
        aoff[i] = sb + OFF_A
                + (uint32_t)((i * 16 + ((j8 & 1) << 3) + lr) * A_STRIDE)
                + (uint32_t)((j8 >> 1) << 4);

    const uint4* gb = reinterpret_cast<const uint4*>(g_b);

    float acc[2][4][4];                // [mtile][cg][frag] = 32 regs
    #pragma unroll
    for (int i = 0; i < 2; i++)
        #pragma unroll
        for (int j = 0; j < 4; j++)
            #pragma unroll
            for (int q = 0; q < 4; q++) acc[i][j][q] = 0.0f;

    uint4 fB[2];
    #pragma unroll
    for (int c = 0; c < 2; c++)
        fB[c] = __ldg(gb + (((wn * 2 + c) << 5) + lid));

    #pragma unroll
    for (int ks = 0; ks < 16; ks++) {
        uint4 nB[2];
        if (ks < 15) {
            #pragma unroll
            for (int c = 0; c < 2; c++)
                nB[c] = __ldg(gb + ((((ks + 1) * 16 + wn * 2 + c) << 5) + lid));
        }
        const uint32_t ka = (uint32_t)(ks * 32);
        uint32_t af[2][4];
        #pragma unroll
        for (int i = 0; i < 2; i++) ldm4(af[i], aoff[i] + ka);
        #pragma unroll
        for (int i = 0; i < 2; i++) {
            #pragma unroll
            for (int cg = 0; cg < 4; cg++) {
                const uint4& bh = fB[cg >> 1];
                const uint32_t b0 = (cg & 1) ? bh.z : bh.x;
                const uint32_t b1v = (cg & 1) ? bh.w : bh.y;
                mma_f16(acc[i][cg], af[i], b0, b1v);
            }
        }
        #pragma unroll
        for (int c = 0; c < 2; c++) fB[c] = nB[c];
    }

    // ---------------- Epilogue (b2 from gmem; L1/L2 resident)
    {
        const size_t rbase = (size_t)blockIdx.x * TILE_M;
        #pragma unroll
        for (int i = 0; i < 2; i++) {
            #pragma unroll
            for (int cg = 0; cg < 4; cg++) {
                const int col = wn * 32 + cg * 8 + tg * 2;
                const float2 bbv = __ldg(reinterpret_cast<const float2*>(b2 + col));
                const size_t r0 = rbase + i * 16 + g;
                *reinterpret_cast<float2*>(out + r0 * TD + col) =
                    make_float2(acc[i][cg][0] + bbv.x, acc[i][cg][1] + bbv.y);
                *reinterpret_cast<float2*>(out + (r0 + 8) * TD + col) =
                    make_float2(acc[i][cg][2] + bbv.x, acc[i][cg][3] + bbv.y);
            }
        }
    }
}

extern "C" void kernel_launch(void* const* d_in, const int* in_sizes, int n_in,
                              void* d_out, int out_size) {
    const int*   y  = (const int*)d_in[0];
    const float* w1 = (const float*)d_in[1];
    const float* b1 = (const float*)d_in[2];
    const float* w2 = (const float*)d_in[3];
    const float* b2 = (const float*)d_in[4];
    float* out = (float*)d_out;
    const int Btot = in_sizes[0] / S;          // 65536 rows
    const int grid = Btot / TILE_M;            // 2048 CTAs

    prep_kernel<<<32, 256>>>(w2);              // w2 fragments
    prep2_kernel<<<1, 512>>>(w1);              // w1 fragments (hi+lo)

    cudaFuncSetAttribute(tte_kernel, cudaFuncAttributeMaxDynamicSharedMemorySize,
                         SMEM_BYTES);
    tte_kernel<<<grid, 256, SMEM_BYTES>>>(y, w1, b1, b2, out);
}

// round 14
// speedup vs baseline: 1.5895x; 1.1071x over previous
#include <cuda_runtime.h>
#include <cuda_fp16.h>
#include <cstdint>

// ---------------------------------------------------------------------------
// TargetTokenEncoder: hist/stats -> MLP(14->256, exact GELU) -> GEMM(256x256)
// Both GEMMs on tensor cores (mma.sync m16n8k16 f16, fp32 accum):
//   stage B: stats(fp16, exact except entropy) @ w1(fp16 hi+lo, 2 passes)
//   stage C: h(fp16) @ w2(fp16, 1 pass)           rel err ~3e-4 total
// R14: TILE_M=64 (halves chip-wide B-fragment traffic, occ 2) + single fused
//     wide prep kernel (was 2 latency-bound launches, ~6us -> ~2us).
// ---------------------------------------------------------------------------

static constexpr int S      = 128;
static constexpr int TD     = 256;
static constexpr int TILE_M = 64;

static constexpr int A_STRIDE = 528;     // 256 fp16 + 8 pad
static constexpr int OFF_A     = 0;      // 64 x 528 = 33792
static constexpr int OFF_STATS = 33792;  // 64 rows x 48B
static constexpr int STATS_STRIDE = 48;  // 16B multiple (ldmatrix-legal)
static constexpr int SMEM_BYTES = 36864; // x2 CTAs = 73728

// w2 fragment scratch: [ks 0..15][cgpair 0..15][lane 0..31][8 fp16]
// Element (e): cg = 2*cgp + (e>>2), k = ks*16 + 2*(L%4) + ((e&2)?8:0) + (e&1),
//              n = cg*8 + L/4, value = w2[k][n]. (layout verified R7..R13)
__device__ __align__(16) __half g_b[16 * 16 * 32 * 8];     // 128KB
// w1 fragment scratch (single ks, K=16 with rows 14,15 zero): hi + lo planes
__device__ __align__(16) __half g_w1h[16 * 32 * 8];        // 8KB
__device__ __align__(16) __half g_w1l[16 * 32 * 8];        // 8KB

__device__ __forceinline__ uint32_t smem_u32(const void* p) {
    uint32_t a;
    asm("{ .reg .u64 t; cvta.to.shared.u64 t, %1; cvt.u32.u64 %0, t; }" : "=r"(a) : "l"(p));
    return a;
}

__device__ __forceinline__ void ldm4(uint32_t* r, uint32_t addr) {
    asm volatile("ldmatrix.sync.aligned.m8n8.x4.shared.b16 {%0,%1,%2,%3}, [%4];"
                 : "=r"(r[0]), "=r"(r[1]), "=r"(r[2]), "=r"(r[3]) : "r"(addr));
}

__device__ __forceinline__ void mma_f16(float* c, const uint32_t* a,
                                        uint32_t b0, uint32_t b1) {
    asm volatile("mma.sync.aligned.m16n8k16.row.col.f32.f16.f16.f32 "
                 "{%0,%1,%2,%3}, {%4,%5,%6,%7}, {%8,%9}, {%0,%1,%2,%3};"
                 : "+f"(c[0]), "+f"(c[1]), "+f"(c[2]), "+f"(c[3])
                 : "r"(a[0]), "r"(a[1]), "r"(a[2]), "r"(a[3]), "r"(b0), "r"(b1));
}

__device__ __forceinline__ float gelu_exact(float x) {
    return 0.5f * x * (1.0f + erff(x * 0.707106781186547524f));
}

// ---------------- fused prep: w2 + w1 -> fp16 fragment scratch (wide)
// 32768 threads; thread t builds half2 #t of g_b (elements 2t, 2t+1).
// Pairs never cross an 8-element group, and within a pair only bit (e&1)
// changes -> kk differs by exactly 1, same n.
__global__ __launch_bounds__(256)
void prep_all(const float* __restrict__ w2, const float* __restrict__ w1) {
    const int t = blockIdx.x * 256 + threadIdx.x;      // 0..32767
    {
        const int el  = t * 2;
        const int grp = el >> 3;                       // (ks<<9)|(cgp<<5)|L
        const int e0  = el & 7;
        const int L   = grp & 31;
        const int cgp = (grp >> 5) & 15;
        const int ks  = grp >> 9;
        const int cg  = cgp * 2 + (e0 >> 2);
        const int n   = cg * 8 + (L >> 2);
        const int kk0 = ks * 16 + 2 * (L & 3) + ((e0 & 2) ? 8 : 0);
        const float v0 = __ldg(w2 + (size_t)kk0 * TD + n);
        const float v1 = __ldg(w2 + (size_t)(kk0 + 1) * TD + n);
        reinterpret_cast<__half2*>(g_b)[t] = __floats2half2_rn(v0, v1);
    }
    if (t < 2048) {                                    // w1 frags: 2048 half2/plane
        const int el  = t * 2;
        const int grp = el >> 3;                       // (cgp<<5)|L
        const int e0  = el & 7;
        const int L   = grp & 31;
        const int cgp = grp >> 5;
        const int cg  = cgp * 2 + (e0 >> 2);
        const int n   = cg * 8 + (L >> 2);
        const int kk0 = 2 * (L & 3) + ((e0 & 2) ? 8 : 0);
        const float v0 = (kk0 < 14)     ? __ldg(w1 + (size_t)kk0 * TD + n) : 0.0f;
        const float v1 = (kk0 + 1 < 14) ? __ldg(w1 + (size_t)(kk0 + 1) * TD + n) : 0.0f;
        const __half h0 = __float2half_rn(v0), h1 = __float2half_rn(v1);
        reinterpret_cast<__half2*>(g_w1h)[t] = __halves2half2(h0, h1);
        reinterpret_cast<__half2*>(g_w1l)[t] =
            __floats2half2_rn(v0 - __half2float(h0), v1 - __half2float(h1));
    }
}

__global__ __launch_bounds__(256, 2)
void tte_kernel(const int* __restrict__ y,
                const float* __restrict__ b1,
                const float* __restrict__ b2, float* __restrict__ out)
{
    extern __shared__ char smem[];
    const uint32_t sb = smem_u32(smem);
    const int tid = threadIdx.x;
    const int wid = tid >> 5;
    const int lid = tid & 31;

    // ---------------- Phase 1: cooperative histogram, 4 threads per row
    {
        const int row = tid >> 2;             // 0..63
        const int sub = tid & 3;
        const int4* p = reinterpret_cast<const int4*>(
            y + ((size_t)blockIdx.x * TILE_M + row) * S) + sub * 8;
        uint32_t a0 = 0, a1 = 0, a2 = 0;      // 4x8-bit packed counters
        #pragma unroll
        for (int i = 0; i < 8; i++) {
            int4 v = __ldg(p + i);
            { int x = v.x; uint32_t b = 1u << ((x & 3) << 3);
              if (x < 4) a0 += b; else if (x < 8) a1 += b; else a2 += b; }
            { int x = v.y; uint32_t b = 1u << ((x & 3) << 3);
              if (x < 4) a0 += b; else if (x < 8) a1 += b; else a2 += b; }
            { int x = v.z; uint32_t b = 1u << ((x & 3) << 3);
              if (x < 4) a0 += b; else if (x < 8) a1 += b; else a2 += b; }
            { int x = v.w; uint32_t b = 1u << ((x & 3) << 3);
              if (x < 4) a0 += b; else if (x < 8) a1 += b; else a2 += b; }
        }
        a0 += __shfl_xor_sync(0xFFFFFFFFu, a0, 1);
        a1 += __shfl_xor_sync(0xFFFFFFFFu, a1, 1);
        a2 += __shfl_xor_sync(0xFFFFFFFFu, a2, 1);
        a0 += __shfl_xor_sync(0xFFFFFFFFu, a0, 2);
        a1 += __shfl_xor_sync(0xFFFFFFFFu, a1, 2);
        a2 += __shfl_xor_sync(0xFFFFFFFFu, a2, 2);
        if (sub == 0) {
            int cnt[10];
            float pr[10];
            #pragma unroll
            for (int c = 0; c < 10; c++) {
                uint32_t a = (c < 4) ? a0 : ((c < 8) ? a1 : a2);
                cnt[c] = (int)((a >> ((c & 3) * 8)) & 0xFF);
                pr[c]  = (float)cnt[c] * (1.0f / 128.0f);   // exact in fp32/fp16
            }
            float ent = 0.0f, pm = 0.0f, nnz = 0.0f;
            #pragma unroll
            for (int c = 0; c < 10; c++) {
                ent -= pr[c] * logf(pr[c] + 1e-6f);         // p==0 -> exactly 0
                pm   = fmaxf(pm, pr[c]);
                nnz += (cnt[c] > 0) ? 1.0f : 0.0f;
            }
            __half2* sr = reinterpret_cast<__half2*>(smem + OFF_STATS
                                                     + row * STATS_STRIDE);
            sr[0] = __floats2half2_rn(pr[0], pr[1]);
            sr[1] = __floats2half2_rn(pr[2], pr[3]);
            sr[2] = __floats2half2_rn(pr[4], pr[5]);
            sr[3] = __floats2half2_rn(pr[6], pr[7]);
            sr[4] = __floats2half2_rn(pr[8], pr[9]);
            sr[5] = __floats2half2_rn(nnz, ent);
            sr[6] = __floats2half2_rn(128.0f, pm);
            sr[7] = __floats2half2_rn(0.0f, 0.0f);
        }
    }
    __syncthreads();

    // warp/lane geometry shared by both GEMMs
    const int wn = wid;                // warp owns cols [wn*32, wn*32+32)
    const int j8 = lid >> 3;
    const int lr = lid & 7;
    const int g  = lid >> 2;
    const int tg = lid & 3;

    // ---------------- Phase 2: stage B = stats[64,16] @ w1[16,256] via HMMA,
    //                  + b1, exact GELU, h -> A smem (fp16)
    {
        const uint4* gwh = reinterpret_cast<const uint4*>(g_w1h);
        const uint4* gwl = reinterpret_cast<const uint4*>(g_w1l);
        uint4 fh[2], fl[2];
        #pragma unroll
        for (int c = 0; c < 2; c++) {
            fh[c] = __ldg(gwh + (((wn * 2 + c) << 5) + lid));
            fl[c] = __ldg(gwl + (((wn * 2 + c) << 5) + lid));
        }
        #pragma unroll
        for (int i = 0; i < 4; i++) {      // 4 m-tiles of 16 rows
            uint32_t afS[4];
            const uint32_t ad = sb + OFF_STATS
                + (uint32_t)((i * 16 + ((j8 & 1) << 3) + lr) * STATS_STRIDE)
                + (uint32_t)((j8 >> 1) << 4);
            ldm4(afS, ad);
            #pragma unroll
            for (int cg = 0; cg < 4; cg++) {
                float accS[4] = {0.0f, 0.0f, 0.0f, 0.0f};
                const uint4& bh = fh[cg >> 1];
                const uint4& bl = fl[cg >> 1];
                const uint32_t h0 = (cg & 1) ? bh.z : bh.x;
                const uint32_t h1 = (cg & 1) ? bh.w : bh.y;
                const uint32_t l0 = (cg & 1) ? bl.z : bl.x;
                const uint32_t l1 = (cg & 1) ? bl.w : bl.y;
                mma_f16(accS, afS, h0, h1);   // S*W1h
                mma_f16(accS, afS, l0, l1);   // S*W1l
                const int col = wn * 32 + cg * 8 + tg * 2;
                const float2 bv = __ldg(reinterpret_cast<const float2*>(b1 + col));
                const int r0 = i * 16 + g;
                *reinterpret_cast<__half2*>(smem + OFF_A
                    + (uint32_t)(r0 * A_STRIDE + col * 2)) =
                    __floats2half2_rn(gelu_exact(accS[0] + bv.x),
                                      gelu_exact(accS[1] + bv.y));
                *reinterpret_cast<__half2*>(smem + OFF_A
                    + (uint32_t)((r0 + 8) * A_STRIDE + col * 2)) =
                    __floats2half2_rn(gelu_exact(accS[2] + bv.x),
                                      gelu_exact(accS[3] + bv.y));
            }
        }
    }
    __syncthreads();   // last barrier — stage C runs barrier-free

    // ---------------- Phase 3: GEMM h[64,256] @ w2 slice, fp16 HMMA (1 pass)
    uint32_t aoff[4];
    #pragma unroll
    for (int i = 0; i < 4; i++)
        aoff[i] = sb + OFF_A
                + (uint32_t)((i * 16 + ((j8 & 1) << 3) + lr) * A_STRIDE)
                + (uint32_t)((j8 >> 1) << 4);

    const uint4* gb = reinterpret_cast<const uint4*>(g_b);

    float acc[4][4][4];                // [mtile][cg][frag] = 64 regs
    #pragma unroll
    for (int i = 0; i < 4; i++)
        #pragma unroll
        for (int j = 0; j < 4; j++)
            #pragma unroll
            for (int q = 0; q < 4; q++) acc[i][j][q] = 0.0f;

    uint4 fB[2];
    #pragma unroll
    for (int c = 0; c < 2; c++)
        fB[c] = __ldg(gb + (((wn * 2 + c) << 5) + lid));

    #pragma unroll
    for (int ks = 0; ks < 16; ks++) {
        uint4 nB[2];
        if (ks < 15) {
            #pragma unroll
            for (int c = 0; c < 2; c++)
                nB[c] = __ldg(gb + ((((ks + 1) * 16 + wn * 2 + c) << 5) + lid));
        }
        const uint32_t ka = (uint32_t)(ks * 32);
        uint32_t af[4][4];
        #pragma unroll
        for (int i = 0; i < 4; i++) ldm4(af[i], aoff[i] + ka);
        #pragma unroll
        for (int i = 0; i < 4; i++) {
            #pragma unroll
            for (int cg = 0; cg < 4; cg++) {
                const uint4& bh = fB[cg >> 1];
                const uint32_t b0 = (cg & 1) ? bh.z : bh.x;
                const uint32_t b1v = (cg & 1) ? bh.w : bh.y;
                mma_f16(acc[i][cg], af[i], b0, b1v);
            }
        }
        #pragma unroll
        for (int c = 0; c < 2; c++) fB[c] = nB[c];
    }

    // ---------------- Epilogue (b2 from gmem; L1/L2 resident)
    {
        const size_t rbase = (size_t)blockIdx.x * TILE_M;
        #pragma unroll
        for (int i = 0; i < 4; i++) {
            #pragma unroll
            for (int cg = 0; cg < 4; cg++) {
                const int col = wn * 32 + cg * 8 + tg * 2;
                const float2 bbv = __ldg(reinterpret_cast<const float2*>(b2 + col));
                const size_t r0 = rbase + i * 16 + g;
                *reinterpret_cast<float2*>(out + r0 * TD + col) =
                    make_float2(acc[i][cg][0] + bbv.x, acc[i][cg][1] + bbv.y);
                *reinterpret_cast<float2*>(out + (r0 + 8) * TD + col) =
                    make_float2(acc[i][cg][2] + bbv.x, acc[i][cg][3] + bbv.y);
            }
        }
    }
}

extern "C" void kernel_launch(void* const* d_in, const int* in_sizes, int n_in,
                              void* d_out, int out_size) {
    const int*   y  = (const int*)d_in[0];
    const float* w1 = (const float*)d_in[1];
    const float* b1 = (const float*)d_in[2];
    const float* w2 = (const float*)d_in[3];
    const float* b2 = (const float*)d_in[4];
    float* out = (float*)d_out;
    const int Btot = in_sizes[0] / S;          // 65536 rows
    const int grid = Btot / TILE_M;            // 1024 CTAs

    prep_all<<<128, 256>>>(w2, w1);            // fused wide prep (~2us)

    cudaFuncSetAttribute(tte_kernel, cudaFuncAttributeMaxDynamicSharedMemorySize,
                         SMEM_BYTES);
    tte_kernel<<<grid, 256, SMEM_BYTES>>>(y, b1, b2, out);
}